// round 9
// baseline (speedup 1.0000x reference)
#include <cuda_runtime.h>
#include <cuda_fp16.h>
#include <math.h>

#define Bq   16
#define Lq   8
#define ACH  2
#define Hq   384
#define Wq   384
#define HWq  (Hq*Wq)
#define SUMN (Bq*Lq)
#define HID  64

// scratch (device globals; no allocation allowed)
__device__ __half g_conf_h[(size_t)SUMN * HWq];   // 37.7 MB
__device__ float  g_conf_sum[SUMN];
__device__ float  g_di_sum[Bq];
__device__ float  g_ov_sum[SUMN];

__device__ __forceinline__ float sigmoidf_fast(float x) {
    return 1.0f / (1.0f + __expf(-x));
}

__device__ __forceinline__ float blockReduceSum(float v) {
    __shared__ float sh[32];
    __syncthreads();                      // safe for repeated calls
    int lane = threadIdx.x & 31, wid = threadIdx.x >> 5;
    #pragma unroll
    for (int o = 16; o; o >>= 1) v += __shfl_down_sync(0xffffffffu, v, o);
    if (lane == 0) sh[wid] = v;
    __syncthreads();
    int nw = (blockDim.x + 31) >> 5;
    v = (threadIdx.x < nw) ? sh[threadIdx.x] : 0.f;
    if (wid == 0) {
        #pragma unroll
        for (int o = 16; o; o >>= 1) v += __shfl_down_sync(0xffffffffu, v, o);
    }
    return v;
}

__global__ void kZero() {
    int t = threadIdx.x;
    if (t < SUMN) { g_conf_sum[t] = 0.f; g_ov_sum[t] = 0.f; }
    if (t < Bq)   g_di_sum[t] = 0.f;
}

// Pass A: conf = sigmoid(max(ch0,ch1)) -> fp16; fp32 per-image sums; demand sums (l==0).
__global__ void kA(const float* __restrict__ psm, const float* __restrict__ req) {
    int img = blockIdx.y;
    int idx = blockIdx.x * blockDim.x + threadIdx.x;   // float4 index < HW/4
    const float4* p0 = reinterpret_cast<const float4*>(psm + (size_t)img * (ACH * HWq));
    const float4* p1 = reinterpret_cast<const float4*>(psm + (size_t)img * (ACH * HWq) + HWq);
    float4 a = p0[idx], b = p1[idx];
    float c0 = sigmoidf_fast(fmaxf(a.x, b.x));
    float c1 = sigmoidf_fast(fmaxf(a.y, b.y));
    float c2 = sigmoidf_fast(fmaxf(a.z, b.z));
    float c3 = sigmoidf_fast(fmaxf(a.w, b.w));

    __half2 h01 = __floats2half2_rn(c0, c1);
    __half2 h23 = __floats2half2_rn(c2, c3);
    uint2 pack;
    pack.x = *reinterpret_cast<unsigned*>(&h01);
    pack.y = *reinterpret_cast<unsigned*>(&h23);
    reinterpret_cast<uint2*>(g_conf_h + (size_t)img * HWq)[idx] = pack;

    float s = blockReduceSum(c0 + c1 + c2 + c3);
    if (threadIdx.x == 0) atomicAdd(&g_conf_sum[img], s);

    if ((img & (Lq - 1)) == 0) {   // demand uses req_mask image at l==0
        float4 d = reinterpret_cast<const float4*>(req + (size_t)img * HWq)[idx];
        float sd = blockReduceSum(d.x + d.y + d.z + d.w);
        if (threadIdx.x == 0) atomicAdd(&g_di_sum[img >> 3], sd);
    }
}

// Pass B: per-image bilinear affine warp of fp16 conf, masked by Di, reduced to overlap sums.
#define KB_PIX 4
__global__ void kB(const float* __restrict__ req, const float* __restrict__ na) {
    int img = blockIdx.y;
    int b = img >> 3, l = img & 7;
    const float* A = na + ((size_t)(b * Lq + 0) * Lq + l) * 6;   // norm_affine[b,0,l]
    float a00 = A[0], a01 = A[1], a02 = A[2];
    float a10 = A[3], a11 = A[4], a12 = A[5];
    const __half* __restrict__ cf = g_conf_h + (size_t)img * HWq;
    const float*  __restrict__ di = req + (size_t)(b * Lq) * HWq;

    float acc = 0.f;
    int base = blockIdx.x * (blockDim.x * KB_PIX) + threadIdx.x;
    #pragma unroll
    for (int k = 0; k < KB_PIX; k++) {
        int pix = base + k * 256;
        int i = pix / Wq, j = pix - i * Wq;
        float gy = -1.f + (float)i * (2.f / (float)(Hq - 1));
        float gx = -1.f + (float)j * (2.f / (float)(Wq - 1));
        float sx = fmaf(a00, gx, fmaf(a01, gy, a02));
        float sy = fmaf(a10, gx, fmaf(a11, gy, a12));
        float px = (sx + 1.f) * (0.5f * (float)(Wq - 1));
        float py = (sy + 1.f) * (0.5f * (float)(Hq - 1));
        float x0f = floorf(px), y0f = floorf(py);
        float wx = px - x0f, wy = py - y0f;
        int x0 = (int)x0f, y0 = (int)y0f;
        int x1 = x0 + 1,   y1 = y0 + 1;
        bool vx0 = (x0 >= 0) & (x0 < Wq);
        bool vx1 = (x1 >= 0) & (x1 < Wq);
        bool vy0 = (y0 >= 0) & (y0 < Hq);
        bool vy1 = (y1 >= 0) & (y1 < Hq);
        float v00 = 0.f, v01 = 0.f, v10 = 0.f, v11 = 0.f;
        if (vy0 & vx0) v00 = __half2float(__ldg(cf + y0 * Wq + x0));
        if (vy0 & vx1) v01 = __half2float(__ldg(cf + y0 * Wq + x1));
        if (vy1 & vx0) v10 = __half2float(__ldg(cf + y1 * Wq + x0));
        if (vy1 & vx1) v11 = __half2float(__ldg(cf + y1 * Wq + x1));
        float warped = v00 * (1.f - wy) * (1.f - wx)
                     + v01 * (1.f - wy) * wx
                     + v10 * wy * (1.f - wx)
                     + v11 * wy * wx;
        acc = fmaf(warped, __ldg(di + pix), acc);
    }
    float s = blockReduceSum(acc);
    if (threadIdx.x == 0) atomicAdd(&g_ov_sum[img], s);
}

// ---------------- Pass C: one block per batch, 8 images in parallel --------
// float offsets within the dynamic smem weight arena
#define O_QW1  0
#define O_QW2  512
#define O_KW1  4608
#define O_KW2  5120
#define O_EW1  9216
#define O_QB1  17408
#define O_QB2  17472
#define O_KB1  17536
#define O_KB2  17600
#define O_EB1  17664
#define O_EW2  17728
#define O_EB2  17792
#define SW_FLOATS 17796
#define SW_BYTES  (SW_FLOATS * 4)

__device__ __forceinline__ void cp4(float* dst, const float* __restrict__ src, int n) {
    for (int i = threadIdx.x; i < (n >> 2); i += blockDim.x)
        reinterpret_cast<float4*>(dst)[i] = reinterpret_cast<const float4*>(src)[i];
}

__global__ void __launch_bounds__(512) kC(
                   const float* __restrict__ na,
                   const float* __restrict__ qW1, const float* __restrict__ qb1,
                   const float* __restrict__ qW2, const float* __restrict__ qb2,
                   const float* __restrict__ kW1, const float* __restrict__ kb1,
                   const float* __restrict__ kW2, const float* __restrict__ kb2,
                   const float* __restrict__ eW1, const float* __restrict__ eb1,
                   const float* __restrict__ eW2, const float* __restrict__ eb2,
                   float* __restrict__ out) {
    extern __shared__ float sw[];
    __shared__ float sh_qh[HID];         // q hidden (relu)
    __shared__ float sh_q[HID];          // q output
    __shared__ float sh_h[Lq][HID];      // k hidden per image
    __shared__ float sh_k[Lq][HID];      // k output per image
    __shared__ float sh_red[Lq][2];

    // cooperative weight staging (512 threads, coalesced float4)
    cp4(sw + O_QW1, qW1, 512);
    cp4(sw + O_QW2, qW2, 4096);
    cp4(sw + O_KW1, kW1, 512);
    cp4(sw + O_KW2, kW2, 4096);
    cp4(sw + O_EW1, eW1, 8192);
    cp4(sw + O_QB1, qb1, 64);
    cp4(sw + O_QB2, qb2, 64);
    cp4(sw + O_KB1, kb1, 64);
    cp4(sw + O_KB2, kb2, 64);
    cp4(sw + O_EB1, eb1, 64);
    cp4(sw + O_EW2, eW2, 64);
    if (threadIdx.x == 0) sw[O_EB2] = eb2[0];

    int b  = blockIdx.x;
    int t  = threadIdx.x;
    int li = t >> 6;          // image within batch: 0..7
    int c  = t & 63;          // MLP column: 0..63
    int img = b * Lq + li;
    const float inv = 1.0f / (float)HWq;
    __syncthreads();

    float demand = g_di_sum[b] * inv;

    // layer-1 for this image's k; group 0 also does q layer-1
    {
        float mc = g_conf_sum[img] * inv;
        float ov = g_ov_sum[img] * inv;
        const float* Aij = na + ((size_t)(b * Lq + 0) * Lq + li) * 6;
        float dx = Aij[2], dy = Aij[5];
        float dist = sqrtf(dx * dx + dy * dy);
        const float* Dl = na + ((size_t)(b * Lq + li) * Lq + li) * 6;
        const float* D0 = na + ((size_t)(b * Lq + 0) * Lq + 0) * 6;
        float yawl = atan2f(Dl[3], Dl[0]);
        float yaw0 = atan2f(D0[3], D0[0]);
        float d = yaw0 - yawl;
        float dyaw = atan2f(sinf(d), cosf(d));
        float cosd = cosf(dyaw), sind = sinf(dyaw);
        float feat[8] = {mc, ov, dx, dy, cosd, sind, dist, demand};

        float hk = sw[O_KB1 + c];
        #pragma unroll
        for (int i = 0; i < 8; i++) hk = fmaf(feat[i], sw[O_KW1 + i * HID + c], hk);
        sh_h[li][c] = fmaxf(hk, 0.f);

        if (li == 0) {
            float mc0 = g_conf_sum[b * Lq] * inv;
            float ego[8] = {mc0, demand, 0.f, 0.f, 1.f, 0.f, 0.f, demand};
            float h = sw[O_QB1 + c];
            #pragma unroll
            for (int i = 0; i < 8; i++) h = fmaf(ego[i], sw[O_QW1 + i * HID + c], h);
            sh_qh[c] = fmaxf(h, 0.f);
        }
    }
    __syncthreads();

    // layer-2: k for all images; q by group 0
    {
        float kv = sw[O_KB2 + c];
        #pragma unroll 16
        for (int i = 0; i < HID; i++) kv = fmaf(sh_h[li][i], sw[O_KW2 + i * HID + c], kv);
        sh_k[li][c] = kv;
        if (li == 0) {
            float qv = sw[O_QB2 + c];
            #pragma unroll 16
            for (int i = 0; i < HID; i++) qv = fmaf(sh_qh[i], sw[O_QW2 + i * HID + c], qv);
            sh_q[c] = qv;
        }
    }
    __syncthreads();

    // e = MLP2([q;k]) -> scalar per image
    {
        float he = sw[O_EB1 + c];
        #pragma unroll 16
        for (int i = 0; i < HID; i++) he = fmaf(sh_q[i], sw[O_EW1 + i * HID + c], he);
        #pragma unroll 16
        for (int i = 0; i < HID; i++) he = fmaf(sh_k[li][i], sw[O_EW1 + (HID + i) * HID + c], he);
        he = fmaxf(he, 0.f);
        float part = he * sw[O_EW2 + c];
        #pragma unroll
        for (int o = 16; o; o >>= 1) part += __shfl_down_sync(0xffffffffu, part, o);
        if ((c & 31) == 0) sh_red[li][c >> 5] = part;
    }
    __syncthreads();
    if (c == 0) {
        float logit = sh_red[li][0] + sh_red[li][1] + sw[O_EB2];
        float r;
        if (li == 0) {
            r = 0.f;   // logits[:,0] = -1e9 -> sigmoid -> 0
        } else {
            r = 1.f / (1.f + expf(-logit));
            r = fminf(fmaxf(r, 0.f), 1.f);
        }
        out[img] = r;
    }
}

extern "C" void kernel_launch(void* const* d_in, const int* in_sizes, int n_in,
                              void* d_out, int out_size) {
    const float* psm = (const float*)d_in[0];
    const float* req = (const float*)d_in[1];
    const float* na  = (const float*)d_in[2];
    // d_in[3] = record_len (unused; always full L)
    const float* qW1 = (const float*)d_in[4];
    const float* qb1 = (const float*)d_in[5];
    const float* qW2 = (const float*)d_in[6];
    const float* qb2 = (const float*)d_in[7];
    const float* kW1 = (const float*)d_in[8];
    const float* kb1 = (const float*)d_in[9];
    const float* kW2 = (const float*)d_in[10];
    const float* kb2 = (const float*)d_in[11];
    const float* eW1 = (const float*)d_in[12];
    const float* eb1 = (const float*)d_in[13];
    const float* eW2 = (const float*)d_in[14];
    const float* eb2 = (const float*)d_in[15];
    float* out = (float*)d_out;

    cudaFuncSetAttribute(kC, cudaFuncAttributeMaxDynamicSharedMemorySize, SW_BYTES);

    kZero<<<1, 256>>>();
    kA<<<dim3(HWq / 4 / 256, SUMN), 256>>>(psm, req);
    kB<<<dim3(HWq / (256 * KB_PIX), SUMN), 256>>>(req, na);
    kC<<<Bq, 512, SW_BYTES>>>(na, qW1, qb1, qW2, qb2, kW1, kb1, kW2, kb2,
                              eW1, eb1, eW2, eb2, out);
}

// round 10
// speedup vs baseline: 1.0100x; 1.0100x over previous
#include <cuda_runtime.h>
#include <cuda_fp16.h>
#include <math.h>

#define Bq   16
#define Lq   8
#define ACH  2
#define Hq   384
#define Wq   384
#define HWq  (Hq*Wq)
#define SUMN (Bq*Lq)
#define HID  64

// scratch (device globals; no allocation allowed)
__device__ __half g_conf_h[(size_t)SUMN * HWq];   // 37.7 MB
__device__ float  g_conf_sum[SUMN];
__device__ float  g_di_sum[Bq];
__device__ float  g_ov_sum[SUMN];

__device__ __forceinline__ float sigmoidf_fast(float x) {
    return 1.0f / (1.0f + __expf(-x));
}

__device__ __forceinline__ float blockReduceSum(float v) {
    __shared__ float sh[32];
    __syncthreads();                      // safe for repeated calls
    int lane = threadIdx.x & 31, wid = threadIdx.x >> 5;
    #pragma unroll
    for (int o = 16; o; o >>= 1) v += __shfl_down_sync(0xffffffffu, v, o);
    if (lane == 0) sh[wid] = v;
    __syncthreads();
    int nw = (blockDim.x + 31) >> 5;
    v = (threadIdx.x < nw) ? sh[threadIdx.x] : 0.f;
    if (wid == 0) {
        #pragma unroll
        for (int o = 16; o; o >>= 1) v += __shfl_down_sync(0xffffffffu, v, o);
    }
    return v;
}

__global__ void kZero() {
    int t = threadIdx.x;
    if (t < SUMN) { g_conf_sum[t] = 0.f; g_ov_sum[t] = 0.f; }
    if (t < Bq)   g_di_sum[t] = 0.f;
}

// Pass A: conf = sigmoid(max(ch0,ch1)) -> fp16; fp32 per-image sums; demand sums (l==0).
__global__ void kA(const float* __restrict__ psm, const float* __restrict__ req) {
    int img = blockIdx.y;
    int idx = blockIdx.x * blockDim.x + threadIdx.x;   // float4 index < HW/4
    const float4* p0 = reinterpret_cast<const float4*>(psm + (size_t)img * (ACH * HWq));
    const float4* p1 = reinterpret_cast<const float4*>(psm + (size_t)img * (ACH * HWq) + HWq);
    float4 a = p0[idx], b = p1[idx];
    float c0 = sigmoidf_fast(fmaxf(a.x, b.x));
    float c1 = sigmoidf_fast(fmaxf(a.y, b.y));
    float c2 = sigmoidf_fast(fmaxf(a.z, b.z));
    float c3 = sigmoidf_fast(fmaxf(a.w, b.w));

    __half2 h01 = __floats2half2_rn(c0, c1);
    __half2 h23 = __floats2half2_rn(c2, c3);
    uint2 pack;
    pack.x = *reinterpret_cast<unsigned*>(&h01);
    pack.y = *reinterpret_cast<unsigned*>(&h23);
    reinterpret_cast<uint2*>(g_conf_h + (size_t)img * HWq)[idx] = pack;

    float s = blockReduceSum(c0 + c1 + c2 + c3);
    if (threadIdx.x == 0) atomicAdd(&g_conf_sum[img], s);

    if ((img & (Lq - 1)) == 0) {   // demand uses req_mask image at l==0
        float4 d = reinterpret_cast<const float4*>(req + (size_t)img * HWq)[idx];
        float sd = blockReduceSum(d.x + d.y + d.z + d.w);
        if (threadIdx.x == 0) atomicAdd(&g_di_sum[img >> 3], sd);
    }
}

// Pass B: per-image bilinear affine warp of fp16 conf, masked by Di, reduced to overlap sums.
#define KB_PIX 4
__global__ void kB(const float* __restrict__ req, const float* __restrict__ na) {
    int img = blockIdx.y;
    int b = img >> 3, l = img & 7;
    const float* A = na + ((size_t)(b * Lq + 0) * Lq + l) * 6;   // norm_affine[b,0,l]
    float a00 = A[0], a01 = A[1], a02 = A[2];
    float a10 = A[3], a11 = A[4], a12 = A[5];
    const __half* __restrict__ cf = g_conf_h + (size_t)img * HWq;
    const float*  __restrict__ di = req + (size_t)(b * Lq) * HWq;

    float acc = 0.f;
    int base = blockIdx.x * (blockDim.x * KB_PIX) + threadIdx.x;
    #pragma unroll
    for (int k = 0; k < KB_PIX; k++) {
        int pix = base + k * 256;
        int i = pix / Wq, j = pix - i * Wq;
        float gy = -1.f + (float)i * (2.f / (float)(Hq - 1));
        float gx = -1.f + (float)j * (2.f / (float)(Wq - 1));
        float sx = fmaf(a00, gx, fmaf(a01, gy, a02));
        float sy = fmaf(a10, gx, fmaf(a11, gy, a12));
        float px = (sx + 1.f) * (0.5f * (float)(Wq - 1));
        float py = (sy + 1.f) * (0.5f * (float)(Hq - 1));
        float x0f = floorf(px), y0f = floorf(py);
        float wx = px - x0f, wy = py - y0f;
        int x0 = (int)x0f, y0 = (int)y0f;
        int x1 = x0 + 1,   y1 = y0 + 1;
        bool vx0 = (x0 >= 0) & (x0 < Wq);
        bool vx1 = (x1 >= 0) & (x1 < Wq);
        bool vy0 = (y0 >= 0) & (y0 < Hq);
        bool vy1 = (y1 >= 0) & (y1 < Hq);
        float v00 = 0.f, v01 = 0.f, v10 = 0.f, v11 = 0.f;
        if (vy0 & vx0) v00 = __half2float(__ldg(cf + y0 * Wq + x0));
        if (vy0 & vx1) v01 = __half2float(__ldg(cf + y0 * Wq + x1));
        if (vy1 & vx0) v10 = __half2float(__ldg(cf + y1 * Wq + x0));
        if (vy1 & vx1) v11 = __half2float(__ldg(cf + y1 * Wq + x1));
        float warped = v00 * (1.f - wy) * (1.f - wx)
                     + v01 * (1.f - wy) * wx
                     + v10 * wy * (1.f - wx)
                     + v11 * wy * wx;
        acc = fmaf(warped, __ldg(di + pix), acc);
    }
    float s = blockReduceSum(acc);
    if (threadIdx.x == 0) atomicAdd(&g_ov_sum[img], s);
}

// ---------------- Pass C: one block per batch, 8 images in parallel --------
// float offsets within the dynamic smem weight arena
#define O_QW1  0
#define O_QW2  512
#define O_KW1  4608
#define O_KW2  5120
#define O_EW1  9216
#define O_QB1  17408
#define O_QB2  17472
#define O_KB1  17536
#define O_KB2  17600
#define O_EB1  17664
#define O_EW2  17728
#define O_EB2  17792
#define SW_FLOATS 17796
#define SW_BYTES  (SW_FLOATS * 4)

__device__ __forceinline__ void cp4(float* dst, const float* __restrict__ src, int n) {
    for (int i = threadIdx.x; i < (n >> 2); i += blockDim.x)
        reinterpret_cast<float4*>(dst)[i] = reinterpret_cast<const float4*>(src)[i];
}

__global__ void __launch_bounds__(512) kC(
                   const float* __restrict__ na,
                   const float* __restrict__ qW1, const float* __restrict__ qb1,
                   const float* __restrict__ qW2, const float* __restrict__ qb2,
                   const float* __restrict__ kW1, const float* __restrict__ kb1,
                   const float* __restrict__ kW2, const float* __restrict__ kb2,
                   const float* __restrict__ eW1, const float* __restrict__ eb1,
                   const float* __restrict__ eW2, const float* __restrict__ eb2,
                   float* __restrict__ out) {
    extern __shared__ float sw[];
    __shared__ float sh_qh[HID];         // q hidden (relu)
    __shared__ float sh_q[HID];          // q output
    __shared__ float sh_h[Lq][HID];      // k hidden per image
    __shared__ float sh_k[Lq][HID];      // k output per image
    __shared__ float sh_red[Lq][2];

    // cooperative weight staging (512 threads, coalesced float4)
    cp4(sw + O_QW1, qW1, 512);
    cp4(sw + O_QW2, qW2, 4096);
    cp4(sw + O_KW1, kW1, 512);
    cp4(sw + O_KW2, kW2, 4096);
    cp4(sw + O_EW1, eW1, 8192);
    cp4(sw + O_QB1, qb1, 64);
    cp4(sw + O_QB2, qb2, 64);
    cp4(sw + O_KB1, kb1, 64);
    cp4(sw + O_KB2, kb2, 64);
    cp4(sw + O_EB1, eb1, 64);
    cp4(sw + O_EW2, eW2, 64);
    if (threadIdx.x == 0) sw[O_EB2] = eb2[0];

    int b  = blockIdx.x;
    int t  = threadIdx.x;
    int li = t >> 6;          // image within batch: 0..7
    int c  = t & 63;          // MLP column: 0..63
    int img = b * Lq + li;
    const float inv = 1.0f / (float)HWq;
    __syncthreads();

    float demand = g_di_sum[b] * inv;

    // layer-1 for this image's k; group 0 also does q layer-1
    {
        float mc = g_conf_sum[img] * inv;
        float ov = g_ov_sum[img] * inv;
        const float* Aij = na + ((size_t)(b * Lq + 0) * Lq + li) * 6;
        float dx = Aij[2], dy = Aij[5];
        float dist = sqrtf(dx * dx + dy * dy);
        const float* Dl = na + ((size_t)(b * Lq + li) * Lq + li) * 6;
        const float* D0 = na + ((size_t)(b * Lq + 0) * Lq + 0) * 6;
        float yawl = atan2f(Dl[3], Dl[0]);
        float yaw0 = atan2f(D0[3], D0[0]);
        float d = yaw0 - yawl;
        float dyaw = atan2f(sinf(d), cosf(d));
        float cosd = cosf(dyaw), sind = sinf(dyaw);
        float feat[8] = {mc, ov, dx, dy, cosd, sind, dist, demand};

        float hk = sw[O_KB1 + c];
        #pragma unroll
        for (int i = 0; i < 8; i++) hk = fmaf(feat[i], sw[O_KW1 + i * HID + c], hk);
        sh_h[li][c] = fmaxf(hk, 0.f);

        if (li == 0) {
            float mc0 = g_conf_sum[b * Lq] * inv;
            float ego[8] = {mc0, demand, 0.f, 0.f, 1.f, 0.f, 0.f, demand};
            float h = sw[O_QB1 + c];
            #pragma unroll
            for (int i = 0; i < 8; i++) h = fmaf(ego[i], sw[O_QW1 + i * HID + c], h);
            sh_qh[c] = fmaxf(h, 0.f);
        }
    }
    __syncthreads();

    // layer-2: k for all images; q by group 0
    {
        float kv = sw[O_KB2 + c];
        #pragma unroll 16
        for (int i = 0; i < HID; i++) kv = fmaf(sh_h[li][i], sw[O_KW2 + i * HID + c], kv);
        sh_k[li][c] = kv;
        if (li == 0) {
            float qv = sw[O_QB2 + c];
            #pragma unroll 16
            for (int i = 0; i < HID; i++) qv = fmaf(sh_qh[i], sw[O_QW2 + i * HID + c], qv);
            sh_q[c] = qv;
        }
    }
    __syncthreads();

    // e = MLP2([q;k]) -> scalar per image
    {
        float he = sw[O_EB1 + c];
        #pragma unroll 16
        for (int i = 0; i < HID; i++) he = fmaf(sh_q[i], sw[O_EW1 + i * HID + c], he);
        #pragma unroll 16
        for (int i = 0; i < HID; i++) he = fmaf(sh_k[li][i], sw[O_EW1 + (HID + i) * HID + c], he);
        he = fmaxf(he, 0.f);
        float part = he * sw[O_EW2 + c];
        #pragma unroll
        for (int o = 16; o; o >>= 1) part += __shfl_down_sync(0xffffffffu, part, o);
        if ((c & 31) == 0) sh_red[li][c >> 5] = part;
    }
    __syncthreads();
    if (c == 0) {
        float logit = sh_red[li][0] + sh_red[li][1] + sw[O_EB2];
        float r;
        if (li == 0) {
            r = 0.f;   // logits[:,0] = -1e9 -> sigmoid -> 0
        } else {
            r = 1.f / (1.f + expf(-logit));
            r = fminf(fmaxf(r, 0.f), 1.f);
        }
        out[img] = r;
    }
}

extern "C" void kernel_launch(void* const* d_in, const int* in_sizes, int n_in,
                              void* d_out, int out_size) {
    const float* psm = (const float*)d_in[0];
    const float* req = (const float*)d_in[1];
    const float* na  = (const float*)d_in[2];
    // d_in[3] = record_len (unused; always full L)
    const float* qW1 = (const float*)d_in[4];
    const float* qb1 = (const float*)d_in[5];
    const float* qW2 = (const float*)d_in[6];
    const float* qb2 = (const float*)d_in[7];
    const float* kW1 = (const float*)d_in[8];
    const float* kb1 = (const float*)d_in[9];
    const float* kW2 = (const float*)d_in[10];
    const float* kb2 = (const float*)d_in[11];
    const float* eW1 = (const float*)d_in[12];
    const float* eb1 = (const float*)d_in[13];
    const float* eW2 = (const float*)d_in[14];
    const float* eb2 = (const float*)d_in[15];
    float* out = (float*)d_out;

    cudaFuncSetAttribute(kC, cudaFuncAttributeMaxDynamicSharedMemorySize, SW_BYTES);

    kZero<<<1, 256>>>();
    kA<<<dim3(HWq / 4 / 256, SUMN), 256>>>(psm, req);
    kB<<<dim3(HWq / (256 * KB_PIX), SUMN), 256>>>(req, na);
    kC<<<Bq, 512, SW_BYTES>>>(na, qW1, qb1, qW2, qb2, kW1, kb1, kW2, kb2,
                              eW1, eb1, eW2, eb2, out);
}

// round 11
// speedup vs baseline: 1.0104x; 1.0003x over previous
#include <cuda_runtime.h>
#include <cuda_fp16.h>
#include <math.h>

#define Bq   16
#define Lq   8
#define ACH  2
#define Hq   384
#define Wq   384
#define HWq  (Hq*Wq)
#define SUMN (Bq*Lq)
#define HID  64

// scratch (device globals; no allocation allowed)
__device__ __half g_conf_h[(size_t)SUMN * HWq];   // 37.7 MB
__device__ float  g_conf_sum[SUMN];
__device__ float  g_di_sum[Bq];
__device__ float  g_ov_sum[SUMN];

__device__ __forceinline__ float sigmoidf_fast(float x) {
    return 1.0f / (1.0f + __expf(-x));
}

__device__ __forceinline__ float blockReduceSum(float v) {
    __shared__ float sh[32];
    __syncthreads();                      // safe for repeated calls
    int lane = threadIdx.x & 31, wid = threadIdx.x >> 5;
    #pragma unroll
    for (int o = 16; o; o >>= 1) v += __shfl_down_sync(0xffffffffu, v, o);
    if (lane == 0) sh[wid] = v;
    __syncthreads();
    int nw = (blockDim.x + 31) >> 5;
    v = (threadIdx.x < nw) ? sh[threadIdx.x] : 0.f;
    if (wid == 0) {
        #pragma unroll
        for (int o = 16; o; o >>= 1) v += __shfl_down_sync(0xffffffffu, v, o);
    }
    return v;
}

__global__ void kZero() {
    int t = threadIdx.x;
    if (t < SUMN) { g_conf_sum[t] = 0.f; g_ov_sum[t] = 0.f; }
    if (t < Bq)   g_di_sum[t] = 0.f;
}

// Pass A: conf = sigmoid(max(ch0,ch1)) -> fp16; fp32 per-image sums; demand sums (l==0).
__global__ void kA(const float* __restrict__ psm, const float* __restrict__ req) {
    int img = blockIdx.y;
    int idx = blockIdx.x * blockDim.x + threadIdx.x;   // float4 index < HW/4
    const float4* p0 = reinterpret_cast<const float4*>(psm + (size_t)img * (ACH * HWq));
    const float4* p1 = reinterpret_cast<const float4*>(psm + (size_t)img * (ACH * HWq) + HWq);
    float4 a = p0[idx], b = p1[idx];
    float c0 = sigmoidf_fast(fmaxf(a.x, b.x));
    float c1 = sigmoidf_fast(fmaxf(a.y, b.y));
    float c2 = sigmoidf_fast(fmaxf(a.z, b.z));
    float c3 = sigmoidf_fast(fmaxf(a.w, b.w));

    __half2 h01 = __floats2half2_rn(c0, c1);
    __half2 h23 = __floats2half2_rn(c2, c3);
    uint2 pack;
    pack.x = *reinterpret_cast<unsigned*>(&h01);
    pack.y = *reinterpret_cast<unsigned*>(&h23);
    reinterpret_cast<uint2*>(g_conf_h + (size_t)img * HWq)[idx] = pack;

    float s = blockReduceSum(c0 + c1 + c2 + c3);
    if (threadIdx.x == 0) atomicAdd(&g_conf_sum[img], s);

    if ((img & (Lq - 1)) == 0) {   // demand uses req_mask image at l==0
        float4 d = reinterpret_cast<const float4*>(req + (size_t)img * HWq)[idx];
        float sd = blockReduceSum(d.x + d.y + d.z + d.w);
        if (threadIdx.x == 0) atomicAdd(&g_di_sum[img >> 3], sd);
    }
}

// Pass B: per-image bilinear affine warp of fp16 conf, masked by Di, reduced to overlap sums.
#define KB_PIX 4
__global__ void kB(const float* __restrict__ req, const float* __restrict__ na) {
    int img = blockIdx.y;
    int b = img >> 3, l = img & 7;
    const float* A = na + ((size_t)(b * Lq + 0) * Lq + l) * 6;   // norm_affine[b,0,l]
    float a00 = A[0], a01 = A[1], a02 = A[2];
    float a10 = A[3], a11 = A[4], a12 = A[5];
    const __half* __restrict__ cf = g_conf_h + (size_t)img * HWq;
    const float*  __restrict__ di = req + (size_t)(b * Lq) * HWq;

    float acc = 0.f;
    int base = blockIdx.x * (blockDim.x * KB_PIX) + threadIdx.x;
    #pragma unroll
    for (int k = 0; k < KB_PIX; k++) {
        int pix = base + k * 256;
        int i = pix / Wq, j = pix - i * Wq;
        float gy = -1.f + (float)i * (2.f / (float)(Hq - 1));
        float gx = -1.f + (float)j * (2.f / (float)(Wq - 1));
        float sx = fmaf(a00, gx, fmaf(a01, gy, a02));
        float sy = fmaf(a10, gx, fmaf(a11, gy, a12));
        float px = (sx + 1.f) * (0.5f * (float)(Wq - 1));
        float py = (sy + 1.f) * (0.5f * (float)(Hq - 1));
        float x0f = floorf(px), y0f = floorf(py);
        float wx = px - x0f, wy = py - y0f;
        int x0 = (int)x0f, y0 = (int)y0f;
        int x1 = x0 + 1,   y1 = y0 + 1;
        bool vx0 = (x0 >= 0) & (x0 < Wq);
        bool vx1 = (x1 >= 0) & (x1 < Wq);
        bool vy0 = (y0 >= 0) & (y0 < Hq);
        bool vy1 = (y1 >= 0) & (y1 < Hq);
        float v00 = 0.f, v01 = 0.f, v10 = 0.f, v11 = 0.f;
        if (vy0 & vx0) v00 = __half2float(__ldg(cf + y0 * Wq + x0));
        if (vy0 & vx1) v01 = __half2float(__ldg(cf + y0 * Wq + x1));
        if (vy1 & vx0) v10 = __half2float(__ldg(cf + y1 * Wq + x0));
        if (vy1 & vx1) v11 = __half2float(__ldg(cf + y1 * Wq + x1));
        float warped = v00 * (1.f - wy) * (1.f - wx)
                     + v01 * (1.f - wy) * wx
                     + v10 * wy * (1.f - wx)
                     + v11 * wy * wx;
        acc = fmaf(warped, __ldg(di + pix), acc);
    }
    float s = blockReduceSum(acc);
    if (threadIdx.x == 0) atomicAdd(&g_ov_sum[img], s);
}

// ---------------- Pass C: one block per batch, 8 images in parallel --------
// float offsets within the dynamic smem weight arena
#define O_QW1  0
#define O_QW2  512
#define O_KW1  4608
#define O_KW2  5120
#define O_EW1  9216
#define O_QB1  17408
#define O_QB2  17472
#define O_KB1  17536
#define O_KB2  17600
#define O_EB1  17664
#define O_EW2  17728
#define O_EB2  17792
#define SW_FLOATS 17796
#define SW_BYTES  (SW_FLOATS * 4)

__device__ __forceinline__ void cp4(float* dst, const float* __restrict__ src, int n) {
    for (int i = threadIdx.x; i < (n >> 2); i += blockDim.x)
        reinterpret_cast<float4*>(dst)[i] = reinterpret_cast<const float4*>(src)[i];
}

__global__ void __launch_bounds__(512) kC(
                   const float* __restrict__ na,
                   const float* __restrict__ qW1, const float* __restrict__ qb1,
                   const float* __restrict__ qW2, const float* __restrict__ qb2,
                   const float* __restrict__ kW1, const float* __restrict__ kb1,
                   const float* __restrict__ kW2, const float* __restrict__ kb2,
                   const float* __restrict__ eW1, const float* __restrict__ eb1,
                   const float* __restrict__ eW2, const float* __restrict__ eb2,
                   float* __restrict__ out) {
    extern __shared__ float sw[];
    __shared__ float sh_qh[HID];         // q hidden (relu)
    __shared__ float sh_q[HID];          // q output
    __shared__ float sh_h[Lq][HID];      // k hidden per image
    __shared__ float sh_k[Lq][HID];      // k output per image
    __shared__ float sh_red[Lq][2];

    // cooperative weight staging (512 threads, coalesced float4)
    cp4(sw + O_QW1, qW1, 512);
    cp4(sw + O_QW2, qW2, 4096);
    cp4(sw + O_KW1, kW1, 512);
    cp4(sw + O_KW2, kW2, 4096);
    cp4(sw + O_EW1, eW1, 8192);
    cp4(sw + O_QB1, qb1, 64);
    cp4(sw + O_QB2, qb2, 64);
    cp4(sw + O_KB1, kb1, 64);
    cp4(sw + O_KB2, kb2, 64);
    cp4(sw + O_EB1, eb1, 64);
    cp4(sw + O_EW2, eW2, 64);
    if (threadIdx.x == 0) sw[O_EB2] = eb2[0];

    int b  = blockIdx.x;
    int t  = threadIdx.x;
    int li = t >> 6;          // image within batch: 0..7
    int c  = t & 63;          // MLP column: 0..63
    int img = b * Lq + li;
    const float inv = 1.0f / (float)HWq;
    __syncthreads();

    float demand = g_di_sum[b] * inv;

    // layer-1 for this image's k; group 0 also does q layer-1
    {
        float mc = g_conf_sum[img] * inv;
        float ov = g_ov_sum[img] * inv;
        const float* Aij = na + ((size_t)(b * Lq + 0) * Lq + li) * 6;
        float dx = Aij[2], dy = Aij[5];
        float dist = sqrtf(dx * dx + dy * dy);
        const float* Dl = na + ((size_t)(b * Lq + li) * Lq + li) * 6;
        const float* D0 = na + ((size_t)(b * Lq + 0) * Lq + 0) * 6;
        float yawl = atan2f(Dl[3], Dl[0]);
        float yaw0 = atan2f(D0[3], D0[0]);
        float d = yaw0 - yawl;
        float dyaw = atan2f(sinf(d), cosf(d));
        float cosd = cosf(dyaw), sind = sinf(dyaw);
        float feat[8] = {mc, ov, dx, dy, cosd, sind, dist, demand};

        float hk = sw[O_KB1 + c];
        #pragma unroll
        for (int i = 0; i < 8; i++) hk = fmaf(feat[i], sw[O_KW1 + i * HID + c], hk);
        sh_h[li][c] = fmaxf(hk, 0.f);

        if (li == 0) {
            float mc0 = g_conf_sum[b * Lq] * inv;
            float ego[8] = {mc0, demand, 0.f, 0.f, 1.f, 0.f, 0.f, demand};
            float h = sw[O_QB1 + c];
            #pragma unroll
            for (int i = 0; i < 8; i++) h = fmaf(ego[i], sw[O_QW1 + i * HID + c], h);
            sh_qh[c] = fmaxf(h, 0.f);
        }
    }
    __syncthreads();

    // layer-2: k for all images; q by group 0
    {
        float kv = sw[O_KB2 + c];
        #pragma unroll 16
        for (int i = 0; i < HID; i++) kv = fmaf(sh_h[li][i], sw[O_KW2 + i * HID + c], kv);
        sh_k[li][c] = kv;
        if (li == 0) {
            float qv = sw[O_QB2 + c];
            #pragma unroll 16
            for (int i = 0; i < HID; i++) qv = fmaf(sh_qh[i], sw[O_QW2 + i * HID + c], qv);
            sh_q[c] = qv;
        }
    }
    __syncthreads();

    // e = MLP2([q;k]) -> scalar per image
    {
        float he = sw[O_EB1 + c];
        #pragma unroll 16
        for (int i = 0; i < HID; i++) he = fmaf(sh_q[i], sw[O_EW1 + i * HID + c], he);
        #pragma unroll 16
        for (int i = 0; i < HID; i++) he = fmaf(sh_k[li][i], sw[O_EW1 + (HID + i) * HID + c], he);
        he = fmaxf(he, 0.f);
        float part = he * sw[O_EW2 + c];
        #pragma unroll
        for (int o = 16; o; o >>= 1) part += __shfl_down_sync(0xffffffffu, part, o);
        if ((c & 31) == 0) sh_red[li][c >> 5] = part;
    }
    __syncthreads();
    if (c == 0) {
        float logit = sh_red[li][0] + sh_red[li][1] + sw[O_EB2];
        float r;
        if (li == 0) {
            r = 0.f;   // logits[:,0] = -1e9 -> sigmoid -> 0
        } else {
            r = 1.f / (1.f + expf(-logit));
            r = fminf(fmaxf(r, 0.f), 1.f);
        }
        out[img] = r;
    }
}

extern "C" void kernel_launch(void* const* d_in, const int* in_sizes, int n_in,
                              void* d_out, int out_size) {
    const float* psm = (const float*)d_in[0];
    const float* req = (const float*)d_in[1];
    const float* na  = (const float*)d_in[2];
    // d_in[3] = record_len (unused; always full L)
    const float* qW1 = (const float*)d_in[4];
    const float* qb1 = (const float*)d_in[5];
    const float* qW2 = (const float*)d_in[6];
    const float* qb2 = (const float*)d_in[7];
    const float* kW1 = (const float*)d_in[8];
    const float* kb1 = (const float*)d_in[9];
    const float* kW2 = (const float*)d_in[10];
    const float* kb2 = (const float*)d_in[11];
    const float* eW1 = (const float*)d_in[12];
    const float* eb1 = (const float*)d_in[13];
    const float* eW2 = (const float*)d_in[14];
    const float* eb2 = (const float*)d_in[15];
    float* out = (float*)d_out;

    cudaFuncSetAttribute(kC, cudaFuncAttributeMaxDynamicSharedMemorySize, SW_BYTES);

    kZero<<<1, 256>>>();
    kA<<<dim3(HWq / 4 / 256, SUMN), 256>>>(psm, req);
    kB<<<dim3(HWq / (256 * KB_PIX), SUMN), 256>>>(req, na);
    kC<<<Bq, 512, SW_BYTES>>>(na, qW1, qb1, qW2, qb2, kW1, kb1, kW2, kb2,
                              eW1, eb1, eW2, eb2, out);
}